// round 9
// baseline (speedup 1.0000x reference)
#include <cuda_runtime.h>
#include <cstdint>

#define NN 16000
#define EE 512000
#define CC 32
#define SHD 9
#define NLAYERS 3
#define NGRAPHS 40
#define TBINS 2200          // bins over [0,5]; knots 5k/11 align at i=200k
#define TSCALE 440.0f       // TBINS/5
#define TILE 64             // edges staged per node per pass

// ---------------- device scratch --------------------------------------------
__device__ float g_bufA[NN * SHD * CC];                  // node state ping (18.4 MB)
__device__ float g_bufB[NN * SHD * CC];                  // node state pong (18.4 MB)
__device__ float g_w[(size_t)EE * CC];                   // per-edge weights, PERMUTED (65.5 MB)
__device__ float g_shp[EE * SHD];                        // sph harmonics, PERMUTED (18.4 MB)
__device__ float g_attrp[EE * 4];                        // edge_attr, PERMUTED (8 MB)
__device__ float g_dp[EE];                               // edge distance, PERMUTED (2 MB)
__device__ int   g_srcp[EE];                             // src node, PERMUTED (2 MB)
__device__ int   g_perm[EE];                             // dst-sorted edge ids (2 MB)
__device__ float g_tab[NLAYERS * (TBINS + 1) * CC];      // radial tables (0.85 MB)
__device__ int   g_cnt[NN];
__device__ int   g_off[NN + 1];
__device__ int   g_cur[NN];
__device__ int   g_bsum[16];

// ---------------- helpers ---------------------------------------------------
__device__ __forceinline__ float fast_silu(float x) {
    return __fdividef(x, 1.0f + __expf(-x));
}

__device__ __forceinline__ void compute_sh(float vx, float vy, float vz, float* shv) {
    float r2 = vx * vx + vy * vy + vz * vz + 1e-12f;
    float rinv = rsqrtf(r2);
    float x = vx * rinv, y = vy * rinv, z = vz * rinv;
    const float s3    = 1.7320508075688772f;
    const float s15   = 3.872983346207417f;
    const float s5_4  = 1.118033988749895f;    // sqrt(5)/2
    const float s15_4 = 1.9364916731037085f;   // sqrt(15)/2
    shv[0] = 1.0f;
    shv[1] = s3 * x;
    shv[2] = s3 * y;
    shv[3] = s3 * z;
    shv[4] = s15 * x * y;
    shv[5] = s15 * y * z;
    shv[6] = s5_4 * (3.0f * z * z - 1.0f);
    shv[7] = s15 * z * x;
    shv[8] = s15_4 * (x * x - y * y);
}

__device__ __forceinline__ void compute_emb(float d, float* emb) {
    const float stepinv = 11.0f / 5.0f;
    const float SQNB = 3.1622776601683795f;   // sqrt(10)
    const float HPI = 1.5707963267948966f;
    #pragma unroll
    for (int i = 0; i < 10; i++) {
        float center = (5.0f / 11.0f) * (float)(i + 1);
        float diff = (d - center) * stepinv;
        float v = 0.0f;
        if (diff > -1.0f && diff < 1.0f) v = __cosf(HPI * diff) * SQNB;
        emb[i] = v;
    }
}

// ---------------- kernel: transpose node_input (coalesced both sides) -------
__global__ __launch_bounds__(288) void tin_kernel(const float* __restrict__ node_input) {
    __shared__ float sm[288];
    int n = blockIdx.x;
    int t = threadIdx.x;
    sm[t] = node_input[n * 288 + t];          // [c][k], linear
    __syncthreads();
    int k = t >> 5, c = t & 31;
    g_bufA[(n * SHD + k) * CC + c] = sm[c * SHD + k];
}

// ---------------- radial table build (all layers) ---------------------------
__global__ void tab_kernel(const float* __restrict__ W1,
                           const float* __restrict__ b1,
                           const float* __restrict__ W2) {
    int bin = blockIdx.x * blockDim.x + threadIdx.x;
    int l = blockIdx.y;
    if (bin > TBINS) return;
    float d = (float)bin * (5.0f / (float)TBINS);
    float emb[10];
    compute_emb(d, emb);
    float w[32];
    #pragma unroll
    for (int c = 0; c < 32; c++) w[c] = 0.0f;
    for (int j = 0; j < 100; j++) {
        float h = b1[l * 100 + j];
        #pragma unroll
        for (int i = 0; i < 10; i++) h += emb[i] * W1[l * 1000 + i * 100 + j];
        h = fast_silu(h);
        const float* w2r = &W2[l * 3200 + j * 32];
        #pragma unroll
        for (int c = 0; c < 32; c++) w[c] += h * w2r[c];
    }
    const float INVS32 = 0.17677669529663687f;  // fold 1/sqrt(32)
    float* out = &g_tab[((size_t)l * (TBINS + 1) + bin) * 32];
    #pragma unroll
    for (int c = 0; c < 32; c++) out[c] = w[c] * INVS32;
}

// ---------------- sort-by-dst pipeline --------------------------------------
__global__ void hist_kernel(const int* __restrict__ eidx) {
    int e = blockIdx.x * blockDim.x + threadIdx.x;
    if (e < EE) atomicAdd(&g_cnt[eidx[e]], 1);
}

__global__ void scan1_kernel() {
    __shared__ int wsum[32];
    int tid = threadIdx.x;
    int b = blockIdx.x;
    int i = b * 1024 + tid;
    int v = (i < NN) ? g_cnt[i] : 0;
    int lane = tid & 31, wid = tid >> 5;
    int x = v;
    #pragma unroll
    for (int o = 1; o < 32; o <<= 1) {
        int t = __shfl_up_sync(0xffffffffu, x, o);
        if (lane >= o) x += t;
    }
    if (lane == 31) wsum[wid] = x;
    __syncthreads();
    if (wid == 0) {
        int y = wsum[lane];
        #pragma unroll
        for (int o = 1; o < 32; o <<= 1) {
            int t = __shfl_up_sync(0xffffffffu, y, o);
            if (lane >= o) y += t;
        }
        wsum[lane] = y;
    }
    __syncthreads();
    int incl = x + ((wid > 0) ? wsum[wid - 1] : 0);
    if (i < NN) g_off[i] = incl - v;
    if (tid == 1023) g_bsum[b] = incl;
}

// merged: each block redundantly prefixes the 16 block sums, then applies
__global__ void scan23_kernel() {
    __shared__ int addv;
    int b = blockIdx.x;
    if (threadIdx.x == 0) {
        int s = 0;
        for (int i = 0; i < b; i++) s += g_bsum[i];
        addv = s;
    }
    __syncthreads();
    int i = b * 1024 + threadIdx.x;
    if (i < NN) {
        int o = g_off[i] + addv;
        g_off[i] = o;
        g_cur[i] = o;
    }
    if (i == 0) g_off[NN] = EE;
}

// scatter: only the 4B permutation index (random write minimized)
__global__ void scatter_kernel(const int* __restrict__ eidx) {
    int e = blockIdx.x * blockDim.x + threadIdx.x;
    if (e < EE) {
        int d = eidx[e];
        int pos = atomicAdd(&g_cur[d], 1);
        g_perm[pos] = e;
    }
}

// ---------------- per-edge weights -------------------------------------------
// l==0: gather via perm (random reads), compute sh/d, write everything permuted.
// l>0 : fully streaming reads of dp/shp/attrp.
__global__ __launch_bounds__(256) void edge_kernel(
        const int* __restrict__ eidx,
        const float* __restrict__ edge_vec,
        const float* __restrict__ edge_attr,
        const float* __restrict__ Wattr,
        int l) {
    __shared__ float sWattr[13 * 32];
    const int tid = threadIdx.x;
    for (int i = tid; i < 416; i += 256) sWattr[i] = Wattr[l * 416 + i];
    __syncthreads();

    const int p = blockIdx.x * 256 + tid;

    float d;
    float shv[9];
    float ea[13];

    if (l == 0) {
        int e = g_perm[p];
        float vx = edge_vec[3 * e + 0];
        float vy = edge_vec[3 * e + 1];
        float vz = edge_vec[3 * e + 2];
        d = sqrtf(vx * vx + vy * vy + vz * vz + 1e-12f);
        compute_sh(vx, vy, vz, shv);
        float4 a4 = *(const float4*)(edge_attr + 4 * e);
        ea[0] = a4.x; ea[1] = a4.y; ea[2] = a4.z; ea[3] = a4.w;
        // persist permuted copies (sequential writes)
        g_srcp[p] = eidx[EE + e];
        g_dp[p] = d;
        #pragma unroll
        for (int k = 0; k < 9; k++) g_shp[p * 9 + k] = shv[k];
        *(float4*)(g_attrp + 4 * p) = a4;
    } else {
        d = g_dp[p];
        #pragma unroll
        for (int k = 0; k < 9; k++) shv[k] = g_shp[p * 9 + k];
        float4 a4 = *(const float4*)(g_attrp + 4 * p);
        ea[0] = a4.x; ea[1] = a4.y; ea[2] = a4.z; ea[3] = a4.w;
    }
    #pragma unroll
    for (int k = 0; k < 9; k++) ea[4 + k] = shv[k];

    // radial weight from table (lerp); d>=5 clamps to exact constant bin
    float u = d * TSCALE;
    if (u > (float)TBINS) u = (float)TBINS;
    int i0 = (int)u;
    float f = u - (float)i0;
    if (i0 >= TBINS) { i0 = TBINS - 1; f = 1.0f; }
    const float* r0 = &g_tab[((size_t)l * (TBINS + 1) + i0) * 32];

    float wr[32];
    #pragma unroll
    for (int q = 0; q < 8; q++) {
        float4 a = *(const float4*)(r0 + q * 4);
        float4 b = *(const float4*)(r0 + 32 + q * 4);
        wr[4 * q + 0] = a.x + f * (b.x - a.x);
        wr[4 * q + 1] = a.y + f * (b.y - a.y);
        wr[4 * q + 2] = a.z + f * (b.z - a.z);
        wr[4 * q + 3] = a.w + f * (b.w - a.w);
    }

    float4* outp4 = (float4*)(g_w + (size_t)p * 32);
    #pragma unroll
    for (int q = 0; q < 8; q++) {
        float aw0 = 0.f, aw1 = 0.f, aw2 = 0.f, aw3 = 0.f;
        #pragma unroll
        for (int i = 0; i < 13; i++) {
            const float* wa = &sWattr[i * 32 + 4 * q];
            float ei = ea[i];
            aw0 += ei * wa[0];
            aw1 += ei * wa[1];
            aw2 += ei * wa[2];
            aw3 += ei * wa[3];
        }
        float4 o;
        o.x = wr[4 * q + 0] * aw0;
        o.y = wr[4 * q + 1] * aw1;
        o.z = wr[4 * q + 2] * aw2;
        o.w = wr[4 * q + 3] * aw3;
        outp4[q] = o;
    }
}

// ---------------- fused aggregate + node update (tile-staged) ---------------
// 288 threads = 4 nodes x 72 (9k x 8c4). Edge metadata staged through shared:
// consume loop has only 2 independent global LDGs per edge (w, x).
__global__ __launch_bounds__(288) void aggnode_kernel(
        const float* __restrict__ node_attr,
        const float* __restrict__ Wself,
        const float* __restrict__ Wout,
        const float* __restrict__ xin,
        float* __restrict__ xout,
        int l) {
    __shared__ float sWs[1024], sWo[1024];
    __shared__ float sx[4][9][32];
    __shared__ float sagg[4][9][32];
    __shared__ float sval[4][32];
    __shared__ int   s_src[4][TILE];
    __shared__ float s_sh[4][TILE * 9];
    __shared__ int   s_ntiles;

    int t = threadIdx.x;
    if (t == 0) s_ntiles = 0;
    for (int i = t; i < 1024; i += 288) {
        sWs[i] = Wself[l * 1024 + i];
        sWo[i] = Wout[l * 1024 + i];
    }

    int sub = t / 72;
    int r = t - sub * 72;
    int k = r >> 3;
    int c4 = r & 7;
    int n = blockIdx.x * 4 + sub;

    int j0 = g_off[n];
    int j1 = g_off[n + 1];
    int deg = j1 - j0;

    *(float4*)&sx[sub][k][c4 * 4] =
        *(const float4*)(xin + (size_t)n * 288 + k * 32 + c4 * 4);
    __syncthreads();
    if (r == 0) atomicMax(&s_ntiles, (deg + TILE - 1) / TILE);
    __syncthreads();
    int ntiles = s_ntiles;

    float4 acc = make_float4(0.f, 0.f, 0.f, 0.f);
    for (int tile = 0; tile < ntiles; tile++) {
        int base = j0 + tile * TILE;
        int cnt = j1 - base;
        if (cnt > TILE) cnt = TILE;
        if (cnt < 0) cnt = 0;

        // stage src + sh cooperatively (coalesced)
        if (r < cnt) s_src[sub][r] = g_srcp[base + r];
        {
            int total = cnt * 9;
            const float* shsrc = g_shp + (size_t)base * 9;
            for (int i = r; i < total; i += 72) s_sh[sub][i] = shsrc[i];
        }
        __syncthreads();

        const float* wbase = g_w + (size_t)base * 32 + c4 * 4;
        #pragma unroll 4
        for (int m = 0; m < cnt; m++) {
            int src = s_src[sub][m];
            float s = s_sh[sub][m * 9 + k];
            float4 w4 = *(const float4*)(wbase + (size_t)m * 32);
            float4 xv = *(const float4*)(xin + (size_t)src * 288 + k * 32 + c4 * 4);
            acc.x = fmaf(xv.x, s * w4.x, acc.x);
            acc.y = fmaf(xv.y, s * w4.y, acc.y);
            acc.z = fmaf(xv.z, s * w4.z, acc.z);
            acc.w = fmaf(xv.w, s * w4.w, acc.w);
        }
        __syncthreads();
    }
    *(float4*)&sagg[sub][k][c4 * 4] = acc;
    __syncthreads();

    // phase 2: t -> (k2, d)
    int k2 = t >> 5;
    int d = t & 31;
    float vals[4];
    #pragma unroll
    for (int s2 = 0; s2 < 4; s2++) {
        float accS = 0.0f, accA = 0.0f;
        #pragma unroll
        for (int c = 0; c < 32; c++) {
            accS += sx[s2][k2][c] * sWs[c * 32 + d];
            accA += sagg[s2][k2][c] * sWo[c * 32 + d];
        }
        float val = node_attr[blockIdx.x * 4 + s2] * accS + accA;
        vals[s2] = val;
        if (k2 == 0) sval[s2][d] = val;
    }
    __syncthreads();
    #pragma unroll
    for (int s2 = 0; s2 < 4; s2++) {
        float s = sval[s2][d];
        float sig = __fdividef(1.0f, 1.0f + __expf(-s));
        float res = (k2 == 0) ? s * sig : vals[s2] * sig;
        xout[((size_t)(blockIdx.x * 4 + s2) * 9 + k2) * 32 + d] = res;
    }
}

// ---------------- output reduction ------------------------------------------
__global__ __launch_bounds__(288) void out_kernel(const int* __restrict__ batch,
                                                  const float* __restrict__ xfin,
                                                  float* __restrict__ out) {
    int t = threadIdx.x;
    int k = t >> 5;             // warp reads contiguous c
    int c = t & 31;
    int n0 = blockIdx.x * 64;
    int n1 = n0 + 64;
    if (n1 > NN) n1 = NN;
    float acc = 0.0f;
    int curg = batch[n0];
    const float INVS400 = 0.05f;  // 1/sqrt(400)
    for (int n = n0; n < n1; n++) {
        int g = batch[n];
        if (g != curg) {
            atomicAdd(&out[curg * 288 + c * 9 + k], acc * INVS400);
            acc = 0.0f;
            curg = g;
        }
        acc += xfin[(n * SHD + k) * CC + c];
    }
    atomicAdd(&out[curg * 288 + c * 9 + k], acc * INVS400);
}

// ---------------- launch ----------------------------------------------------
extern "C" void kernel_launch(void* const* d_in, const int* in_sizes, int n_in,
                              void* d_out, int out_size) {
    const float* node_input = (const float*)d_in[0];
    const float* node_attr  = (const float*)d_in[1];
    const float* edge_vec   = (const float*)d_in[2];
    const float* edge_attr  = (const float*)d_in[3];
    const float* W1         = (const float*)d_in[4];
    const float* b1         = (const float*)d_in[5];
    const float* W2         = (const float*)d_in[6];
    const float* Wattr      = (const float*)d_in[7];
    const float* Wself      = (const float*)d_in[8];
    const float* Wout       = (const float*)d_in[9];
    const int*   eidx       = (const int*)d_in[10];
    const int*   batch      = (const int*)d_in[11];
    float* out = (float*)d_out;

    float* bufA; cudaGetSymbolAddress((void**)&bufA, g_bufA);
    float* bufB; cudaGetSymbolAddress((void**)&bufB, g_bufB);
    int*   cntp; cudaGetSymbolAddress((void**)&cntp, g_cnt);

    tin_kernel<<<NN, 288>>>(node_input);

    {
        dim3 g((TBINS + 1 + 127) / 128, NLAYERS);
        tab_kernel<<<g, 128>>>(W1, b1, W2);
    }

    cudaMemsetAsync(cntp, 0, NN * sizeof(int));
    hist_kernel<<<EE / 256, 256>>>(eidx);
    scan1_kernel<<<16, 1024>>>();
    scan23_kernel<<<16, 1024>>>();
    scatter_kernel<<<EE / 256, 256>>>(eidx);

    float* xin = bufA;
    float* xout = bufB;
    for (int l = 0; l < NLAYERS; l++) {
        edge_kernel<<<EE / 256, 256>>>(eidx, edge_vec, edge_attr, Wattr, l);
        aggnode_kernel<<<NN / 4, 288>>>(node_attr, Wself, Wout, xin, xout, l);
        float* tmp = xin; xin = xout; xout = tmp;
    }

    cudaMemsetAsync(out, 0, (size_t)out_size * sizeof(float));
    out_kernel<<<(NN + 63) / 64, 288>>>(batch, xin, out);
}

// round 10
// speedup vs baseline: 1.2403x; 1.2403x over previous
#include <cuda_runtime.h>
#include <cstdint>

#define NN 16000
#define EE 512000
#define CC 32
#define SHD 9
#define NLAYERS 3
#define NGRAPHS 40
#define TBINS 2200          // bins over [0,5]; knots 5k/11 align at i=200k
#define TSCALE 440.0f       // TBINS/5
#define WPB 8               // warps (nodes) per block in aggnode

// ---------------- device scratch --------------------------------------------
__device__ float g_bufA[NN * SHD * CC];                  // node state ping (18.4 MB)
__device__ float g_bufB[NN * SHD * CC];                  // node state pong (18.4 MB)
__device__ float g_shp[EE * SHD];                        // sph harmonics, PERMUTED (18.4 MB)
__device__ float g_attrp[EE * 4];                        // edge_attr, PERMUTED (8 MB)
__device__ float g_dp[EE];                               // edge distance, PERMUTED (2 MB)
__device__ int   g_srcp[EE];                             // src node, PERMUTED (2 MB)
__device__ int   g_perm[EE];                             // dst-sorted edge ids (2 MB)
__device__ float g_tab[NLAYERS * (TBINS + 1) * CC];      // radial tables (0.85 MB)
__device__ int   g_cnt[NN];
__device__ int   g_off[NN + 1];
__device__ int   g_cur[NN];
__device__ int   g_bsum[16];

// ---------------- helpers ---------------------------------------------------
__device__ __forceinline__ float fast_silu(float x) {
    return __fdividef(x, 1.0f + __expf(-x));
}

__device__ __forceinline__ void compute_sh(float vx, float vy, float vz, float* shv) {
    float r2 = vx * vx + vy * vy + vz * vz + 1e-12f;
    float rinv = rsqrtf(r2);
    float x = vx * rinv, y = vy * rinv, z = vz * rinv;
    const float s3    = 1.7320508075688772f;
    const float s15   = 3.872983346207417f;
    const float s5_4  = 1.118033988749895f;    // sqrt(5)/2
    const float s15_4 = 1.9364916731037085f;   // sqrt(15)/2
    shv[0] = 1.0f;
    shv[1] = s3 * x;
    shv[2] = s3 * y;
    shv[3] = s3 * z;
    shv[4] = s15 * x * y;
    shv[5] = s15 * y * z;
    shv[6] = s5_4 * (3.0f * z * z - 1.0f);
    shv[7] = s15 * z * x;
    shv[8] = s15_4 * (x * x - y * y);
}

__device__ __forceinline__ void compute_emb(float d, float* emb) {
    const float stepinv = 11.0f / 5.0f;
    const float SQNB = 3.1622776601683795f;   // sqrt(10)
    const float HPI = 1.5707963267948966f;
    #pragma unroll
    for (int i = 0; i < 10; i++) {
        float center = (5.0f / 11.0f) * (float)(i + 1);
        float diff = (d - center) * stepinv;
        float v = 0.0f;
        if (diff > -1.0f && diff < 1.0f) v = __cosf(HPI * diff) * SQNB;
        emb[i] = v;
    }
}

// ---------------- kernel: transpose node_input (coalesced both sides) -------
__global__ __launch_bounds__(288) void tin_kernel(const float* __restrict__ node_input) {
    __shared__ float sm[288];
    int n = blockIdx.x;
    int t = threadIdx.x;
    sm[t] = node_input[n * 288 + t];          // [c][k], linear
    __syncthreads();
    int k = t >> 5, c = t & 31;
    g_bufA[(n * SHD + k) * CC + c] = sm[c * SHD + k];
}

// ---------------- radial table build (all layers) ---------------------------
__global__ void tab_kernel(const float* __restrict__ W1,
                           const float* __restrict__ b1,
                           const float* __restrict__ W2) {
    int bin = blockIdx.x * blockDim.x + threadIdx.x;
    int l = blockIdx.y;
    if (bin > TBINS) return;
    float d = (float)bin * (5.0f / (float)TBINS);
    float emb[10];
    compute_emb(d, emb);
    float w[32];
    #pragma unroll
    for (int c = 0; c < 32; c++) w[c] = 0.0f;
    for (int j = 0; j < 100; j++) {
        float h = b1[l * 100 + j];
        #pragma unroll
        for (int i = 0; i < 10; i++) h += emb[i] * W1[l * 1000 + i * 100 + j];
        h = fast_silu(h);
        const float* w2r = &W2[l * 3200 + j * 32];
        #pragma unroll
        for (int c = 0; c < 32; c++) w[c] += h * w2r[c];
    }
    const float INVS32 = 0.17677669529663687f;  // fold 1/sqrt(32)
    float* out = &g_tab[((size_t)l * (TBINS + 1) + bin) * 32];
    #pragma unroll
    for (int c = 0; c < 32; c++) out[c] = w[c] * INVS32;
}

// ---------------- sort-by-dst pipeline --------------------------------------
__global__ void hist_kernel(const int* __restrict__ eidx) {
    int e = blockIdx.x * blockDim.x + threadIdx.x;
    if (e < EE) atomicAdd(&g_cnt[eidx[e]], 1);
}

__global__ void scan1_kernel() {
    __shared__ int wsum[32];
    int tid = threadIdx.x;
    int b = blockIdx.x;
    int i = b * 1024 + tid;
    int v = (i < NN) ? g_cnt[i] : 0;
    int lane = tid & 31, wid = tid >> 5;
    int x = v;
    #pragma unroll
    for (int o = 1; o < 32; o <<= 1) {
        int t = __shfl_up_sync(0xffffffffu, x, o);
        if (lane >= o) x += t;
    }
    if (lane == 31) wsum[wid] = x;
    __syncthreads();
    if (wid == 0) {
        int y = wsum[lane];
        #pragma unroll
        for (int o = 1; o < 32; o <<= 1) {
            int t = __shfl_up_sync(0xffffffffu, y, o);
            if (lane >= o) y += t;
        }
        wsum[lane] = y;
    }
    __syncthreads();
    int incl = x + ((wid > 0) ? wsum[wid - 1] : 0);
    if (i < NN) g_off[i] = incl - v;
    if (tid == 1023) g_bsum[b] = incl;
}

__global__ void scan23_kernel() {
    __shared__ int addv;
    int b = blockIdx.x;
    if (threadIdx.x == 0) {
        int s = 0;
        for (int i = 0; i < b; i++) s += g_bsum[i];
        addv = s;
    }
    __syncthreads();
    int i = b * 1024 + threadIdx.x;
    if (i < NN) {
        int o = g_off[i] + addv;
        g_off[i] = o;
        g_cur[i] = o;
    }
    if (i == 0) g_off[NN] = EE;
}

__global__ void scatter_kernel(const int* __restrict__ eidx) {
    int e = blockIdx.x * blockDim.x + threadIdx.x;
    if (e < EE) {
        int d = eidx[e];
        int pos = atomicAdd(&g_cur[d], 1);
        g_perm[pos] = e;
    }
}

// ---------------- prep: materialize permuted edge payload (once) ------------
__global__ __launch_bounds__(256) void prep_kernel(const int* __restrict__ eidx,
                                                    const float* __restrict__ edge_vec,
                                                    const float* __restrict__ edge_attr) {
    int p = blockIdx.x * 256 + threadIdx.x;
    if (p >= EE) return;
    int e = g_perm[p];
    float vx = edge_vec[3 * e + 0];
    float vy = edge_vec[3 * e + 1];
    float vz = edge_vec[3 * e + 2];
    float d = sqrtf(vx * vx + vy * vy + vz * vz + 1e-12f);
    float shv[9];
    compute_sh(vx, vy, vz, shv);
    g_srcp[p] = eidx[EE + e];
    g_dp[p] = d;
    #pragma unroll
    for (int k = 0; k < 9; k++) g_shp[p * 9 + k] = shv[k];
    float4 a4 = *(const float4*)(edge_attr + 4 * e);
    *(float4*)(g_attrp + 4 * p) = a4;
}

// ---------------- fused edge-weight + aggregate + node update ---------------
// One warp per node, lanes = channels c. All global accesses coalesced or
// uniform-broadcast. No g_w intermediate; radial table lerp + ea@Wattr fused.
__global__ __launch_bounds__(32 * WPB) void aggnode_kernel(
        const float* __restrict__ node_attr,
        const float* __restrict__ Wself,
        const float* __restrict__ Wout,
        const float* __restrict__ Wattr,
        const float* __restrict__ xin,
        float* __restrict__ xout,
        int l) {
    __shared__ float sWs[1024], sWo[1024], sWa[416];
    __shared__ float sX[WPB][9][32];
    __shared__ float sA[WPB][9][32];

    int t = threadIdx.x;
    int lane = t & 31;
    int wid = t >> 5;
    for (int i = t; i < 1024; i += 32 * WPB) {
        sWs[i] = Wself[l * 1024 + i];
        sWo[i] = Wout[l * 1024 + i];
    }
    for (int i = t; i < 416; i += 32 * WPB) sWa[i] = Wattr[l * 416 + i];
    __syncthreads();

    int n = blockIdx.x * WPB + wid;

    // self features (lane = c)
    float sxv[9];
    const float* xself = xin + (size_t)n * 288 + lane;
    #pragma unroll
    for (int k = 0; k < 9; k++) sxv[k] = xself[k * 32];

    const float* tabL = g_tab + (size_t)l * (TBINS + 1) * 32;
    int j0 = g_off[n];
    int j1 = g_off[n + 1];

    float acc[9];
    #pragma unroll
    for (int k = 0; k < 9; k++) acc[k] = 0.0f;

    for (int j = j0; j < j1; j++) {
        int src = g_srcp[j];                       // uniform
        float d = g_dp[j];                         // uniform
        float sh9 = (lane < 9) ? g_shp[j * 9 + lane] : 0.0f;
        float4 at = *(const float4*)(g_attrp + 4 * j);  // uniform

        float shk[9];
        #pragma unroll
        for (int k = 0; k < 9; k++) shk[k] = __shfl_sync(0xffffffffu, sh9, k);

        // aw[lane] = ea @ Wattr  (ea = [attr4, sh9])
        float aw = at.x * sWa[lane];
        aw = fmaf(at.y, sWa[32 + lane], aw);
        aw = fmaf(at.z, sWa[64 + lane], aw);
        aw = fmaf(at.w, sWa[96 + lane], aw);
        #pragma unroll
        for (int k = 0; k < 9; k++) aw = fmaf(shk[k], sWa[(4 + k) * 32 + lane], aw);

        // radial lerp (includes 1/sqrt(32))
        float u = d * TSCALE;
        if (u > (float)TBINS) u = (float)TBINS;
        int i0 = (int)u;
        float f = u - (float)i0;
        if (i0 >= TBINS) { i0 = TBINS - 1; f = 1.0f; }
        float a = tabL[i0 * 32 + lane];
        float b = tabL[(i0 + 1) * 32 + lane];
        float w = (a + f * (b - a)) * aw;

        const float* xr = xin + (size_t)src * 288 + lane;
        #pragma unroll
        for (int k = 0; k < 9; k++)
            acc[k] = fmaf(xr[k * 32], shk[k] * w, acc[k]);
    }

    // phase 2: per-warp 32x32 mixes + gating (lane = d)
    #pragma unroll
    for (int k = 0; k < 9; k++) {
        sX[wid][k][lane] = sxv[k];
        sA[wid][k][lane] = acc[k];
    }
    __syncwarp();

    float na = node_attr[n];
    float val[9];
    #pragma unroll
    for (int k = 0; k < 9; k++) {
        float aS = 0.0f, aA = 0.0f;
        #pragma unroll
        for (int c = 0; c < 32; c++) {
            aS = fmaf(sX[wid][k][c], sWs[c * 32 + lane], aS);
            aA = fmaf(sA[wid][k][c], sWo[c * 32 + lane], aA);
        }
        val[k] = na * aS + aA;
    }
    float sig = __fdividef(1.0f, 1.0f + __expf(-val[0]));
    float* outr = xout + (size_t)n * 288 + lane;
    outr[0] = val[0] * sig;
    #pragma unroll
    for (int k = 1; k < 9; k++) outr[k * 32] = val[k] * sig;
}

// ---------------- output reduction ------------------------------------------
__global__ __launch_bounds__(288) void out_kernel(const int* __restrict__ batch,
                                                  const float* __restrict__ xfin,
                                                  float* __restrict__ out) {
    int t = threadIdx.x;
    int k = t >> 5;             // warp reads contiguous c
    int c = t & 31;
    int n0 = blockIdx.x * 64;
    int n1 = n0 + 64;
    if (n1 > NN) n1 = NN;
    float acc = 0.0f;
    int curg = batch[n0];
    const float INVS400 = 0.05f;  // 1/sqrt(400)
    for (int n = n0; n < n1; n++) {
        int g = batch[n];
        if (g != curg) {
            atomicAdd(&out[curg * 288 + c * 9 + k], acc * INVS400);
            acc = 0.0f;
            curg = g;
        }
        acc += xfin[(n * SHD + k) * CC + c];
    }
    atomicAdd(&out[curg * 288 + c * 9 + k], acc * INVS400);
}

// ---------------- launch ----------------------------------------------------
extern "C" void kernel_launch(void* const* d_in, const int* in_sizes, int n_in,
                              void* d_out, int out_size) {
    const float* node_input = (const float*)d_in[0];
    const float* node_attr  = (const float*)d_in[1];
    const float* edge_vec   = (const float*)d_in[2];
    const float* edge_attr  = (const float*)d_in[3];
    const float* W1         = (const float*)d_in[4];
    const float* b1         = (const float*)d_in[5];
    const float* W2         = (const float*)d_in[6];
    const float* Wattr      = (const float*)d_in[7];
    const float* Wself      = (const float*)d_in[8];
    const float* Wout       = (const float*)d_in[9];
    const int*   eidx       = (const int*)d_in[10];
    const int*   batch      = (const int*)d_in[11];
    float* out = (float*)d_out;

    float* bufA; cudaGetSymbolAddress((void**)&bufA, g_bufA);
    float* bufB; cudaGetSymbolAddress((void**)&bufB, g_bufB);
    int*   cntp; cudaGetSymbolAddress((void**)&cntp, g_cnt);

    tin_kernel<<<NN, 288>>>(node_input);

    {
        dim3 g((TBINS + 1 + 127) / 128, NLAYERS);
        tab_kernel<<<g, 128>>>(W1, b1, W2);
    }

    cudaMemsetAsync(cntp, 0, NN * sizeof(int));
    hist_kernel<<<EE / 256, 256>>>(eidx);
    scan1_kernel<<<16, 1024>>>();
    scan23_kernel<<<16, 1024>>>();
    scatter_kernel<<<EE / 256, 256>>>(eidx);
    prep_kernel<<<EE / 256, 256>>>(eidx, edge_vec, edge_attr);

    float* xin = bufA;
    float* xout = bufB;
    for (int l = 0; l < NLAYERS; l++) {
        aggnode_kernel<<<NN / WPB, 32 * WPB>>>(node_attr, Wself, Wout, Wattr,
                                               xin, xout, l);
        float* tmp = xin; xin = xout; xout = tmp;
    }

    cudaMemsetAsync(out, 0, (size_t)out_size * sizeof(float));
    out_kernel<<<(NN + 63) / 64, 288>>>(batch, xin, out);
}